// round 7
// baseline (speedup 1.0000x reference)
#include <cuda_runtime.h>
#include <math.h>

// Tropical (max-plus) depthwise 5x5 conv, stride 1, pad 2 (-inf), dilation 1.
// x: [8,32,224,224] f32, kernel: [32,1,5,5] f32, out same shape.
// out[b,c,h,w] = max_{i,j} ( x_pad[b,c,h+i,w+j] + kflip[c,i,j] ),
// kflip[c,i,j] = kernel[c,0,4-i,4-j].
//
// R6: scalar FADD/FMNMX taps (R5 packed-f32x2 reverted: regression).
//  - One-row software pipeline: row r+1's two float4 quads load into vn[]
//    while row r computes from vc[] -> hides L1/L2 latency behind ~170 math
//    instrs per row.
//  - 1600 threads per plane (57x28 = 1596 used + 4 idle) so each warp's 32
//    threads share one plane (1600 % 32 == 0): plane/c warp-uniform again ->
//    broadcast weight loads, uniform-register promotion possible.
//  - 4-wide x 8-tall tile, cyclic 5-row accumulator window, 2 aligned float4
//    loads per input row, predicated float2 stores.

#define HW 224
#define NEG_INF (-INFINITY)

__device__ __forceinline__ void load_row(const float* __restrict__ xp,
                                         int gr, int colL,
                                         bool ldL, bool ldR,
                                         float v[8])
{
    if (gr >= 0 && gr < HW) {
        const float* rowp = xp + gr * HW + colL;
        if (ldL) {
            const float4 t = *reinterpret_cast<const float4*>(rowp);
            v[0] = t.x; v[1] = t.y; v[2] = t.z; v[3] = t.w;
        } else {
            v[0] = NEG_INF; v[1] = NEG_INF; v[2] = NEG_INF; v[3] = NEG_INF;
        }
        if (ldR) {
            const float4 t = *reinterpret_cast<const float4*>(rowp + 4);
            v[4] = t.x; v[5] = t.y; v[6] = t.z; v[7] = t.w;
        } else {
            v[4] = NEG_INF; v[5] = NEG_INF; v[6] = NEG_INF; v[7] = NEG_INF;
        }
    } else {
#pragma unroll
        for (int q = 0; q < 8; q++) v[q] = NEG_INF;
    }
}

__global__ __launch_bounds__(256, 4) void tropical_conv_kernel(
    const float* __restrict__ x,
    const float* __restrict__ w,
    float* __restrict__ out)
{
    const int gid   = blockIdx.x * blockDim.x + threadIdx.x;
    const int plane = gid >> 6 >> 4 >> 0 ? gid / 1600 : 0;  // gid / 1600
    const int rem   = gid - (gid / 1600) * 1600;
    if (rem >= 1596) return;                // 4 idle threads per plane
    const int rg    = rem / 57;             // row group 0..27 (output rows rg*8..rg*8+7)
    const int tx    = rem - rg * 57;        // col group 0..56
    const int c     = (gid / 1600) & 31;    // plane = b*32 + c (warp-uniform)

    // Flipped weights (warp-uniform -> broadcast loads)
    float wf[25];
#pragma unroll
    for (int i = 0; i < 5; i++)
#pragma unroll
        for (int j = 0; j < 5; j++)
            wf[i * 5 + j] = __ldg(&w[c * 25 + (4 - i) * 5 + (4 - j)]);

    const float* xp = x + (size_t)(gid / 1600) * (HW * HW);
    float* op_base  = out + (size_t)(gid / 1600) * (HW * HW) + (rg * 8) * HW + (tx * 4 - 2);

    const int colL = tx * 4 - 4;            // left aligned quad: cols colL..colL+3
    const int row0 = rg * 8 - 2;            // first input row of the 12-row window

    const bool ldL = (tx > 0);
    const bool ldR = (tx < 56);

    float acc[5][4];                        // cyclic window of 5 active output rows
    float vc[8], vn[8];

    load_row(xp, row0, colL, ldL, ldR, vc); // prologue: row 0 of the window

#pragma unroll
    for (int r = 0; r < 12; r++) {
        // Prefetch next input row while computing the current one.
        if (r < 11)
            load_row(xp, row0 + r + 1, colL, ldL, ldR, vn);

        // Output row oh = r begins accumulating at this input row.
        if (r < 8) {
            const int s = r % 5;
#pragma unroll
            for (int q = 0; q < 4; q++) acc[s][q] = NEG_INF;
        }

        // Input row r contributes to output rows oh = r - i, i = 0..4.
#pragma unroll
        for (int i = 0; i < 5; i++) {
            const int oh = r - i;
            if (oh >= 0 && oh < 8) {        // compile-time after unroll
                const int s = oh % 5;
#pragma unroll
                for (int j = 0; j < 5; j++) {
                    const float wv = wf[i * 5 + j];
#pragma unroll
                    for (int q = 0; q < 4; q++)
                        acc[s][q] = fmaxf(acc[s][q], vc[q + j] + wv);
                }
            }
        }

        // Output row oh = r - 4 is complete after this input row: store it.
        if (r >= 4) {
            const int oh = r - 4;
            const int s  = oh % 5;
            float* orow  = op_base + oh * HW;
            if (tx > 0) {
                float2 t; t.x = acc[s][0]; t.y = acc[s][1];
                *reinterpret_cast<float2*>(orow) = t;
            }
            if (tx < 56) {
                float2 t; t.x = acc[s][2]; t.y = acc[s][3];
                *reinterpret_cast<float2*>(orow + 2) = t;
            }
        }

        // Rotate the pipeline (register renaming; no data movement in SASS).
        if (r < 11) {
#pragma unroll
            for (int q = 0; q < 8; q++) vc[q] = vn[q];
        }
    }
}

extern "C" void kernel_launch(void* const* d_in, const int* in_sizes, int n_in,
                              void* d_out, int out_size)
{
    const float* x = (const float*)d_in[0];
    const float* w = (const float*)d_in[1];
    float* out     = (float*)d_out;
    // 256 planes * 1600 threads (1596 active) = 409600 threads = 1600 blocks
    tropical_conv_kernel<<<1600, 256>>>(x, w, out);
}

// round 8
// speedup vs baseline: 1.1115x; 1.1115x over previous
#include <cuda_runtime.h>
#include <math.h>

// Tropical (max-plus) depthwise 5x5 conv, stride 1, pad 2 (-inf), dilation 1.
// x: [8,32,224,224] f32, kernel: [32,1,5,5] f32, out same shape.
// out[b,c,h,w] = max_{i,j} ( x_pad[b,c,h+i,w+j] + kflip[c,i,j] ),
// kflip[c,i,j] = kernel[c,0,4-i,4-j].
//
// R7 = best (R4-design, 33.5us) kernel + FMNMX3-friendly max trees:
//  - per (i, output-row, q): 5 independent FADDs then a balanced max tree
//    written as fmaxf(fmaxf(a,b),c) so ptxas can fuse to 3-input FMNMX3
//    (sm_90+). Worst case (no fusion) it still cuts the acc dependence
//    depth from 5 to 1 per weight row.
//  - accumulator init fused into the i==0 tap block (first contribution to
//    output row oh always happens at i==0), removing the -inf init + 1 max.
//  - otherwise identical: 4-wide x 8-tall streaming tile, cyclic 5-row
//    accumulator window, 2 aligned float4 loads/row, predicated float2
//    stores, 57 col-groups x 28 row-groups x 256 planes, 1596 blocks of 256,
//    __launch_bounds__(256,4) -> 64 regs / 4 CTAs per SM.

#define HW 224
#define NEG_INF (-INFINITY)

__global__ __launch_bounds__(256, 4) void tropical_conv_kernel(
    const float* __restrict__ x,
    const float* __restrict__ w,
    float* __restrict__ out)
{
    const int gid   = blockIdx.x * blockDim.x + threadIdx.x;
    const int plane = gid / 1596;           // b*32 + c, 0..255
    const int rem   = gid - plane * 1596;
    const int rg    = rem / 57;             // row group 0..27 (output rows rg*8..rg*8+7)
    const int tx    = rem - rg * 57;        // col group 0..56
    const int c     = plane & 31;

    // Flipped weights
    float wf[25];
#pragma unroll
    for (int i = 0; i < 5; i++)
#pragma unroll
        for (int j = 0; j < 5; j++)
            wf[i * 5 + j] = __ldg(&w[c * 25 + (4 - i) * 5 + (4 - j)]);

    const float* xp = x + (size_t)plane * (HW * HW);
    float* op_base  = out + (size_t)plane * (HW * HW) + (rg * 8) * HW + (tx * 4 - 2);

    const int colL = tx * 4 - 4;            // left aligned quad: cols colL..colL+3
    const int row0 = rg * 8 - 2;            // first input row of the 12-row window

    const bool ldL = (tx > 0);
    const bool ldR = (tx < 56);

    float acc[5][4];                        // cyclic window of 5 active output rows

#pragma unroll
    for (int r = 0; r < 12; r++) {
        const int gr = row0 + r;
        const bool rowok = (gr >= 0) && (gr < HW);

        float v[8];                         // input cols colL .. colL+7
        if (rowok) {
            const float* rowp = xp + gr * HW + colL;
            if (ldL) {
                const float4 t = *reinterpret_cast<const float4*>(rowp);
                v[0] = t.x; v[1] = t.y; v[2] = t.z; v[3] = t.w;
            } else {
                v[0] = NEG_INF; v[1] = NEG_INF; v[2] = NEG_INF; v[3] = NEG_INF;
            }
            if (ldR) {
                const float4 t = *reinterpret_cast<const float4*>(rowp + 4);
                v[4] = t.x; v[5] = t.y; v[6] = t.z; v[7] = t.w;
            } else {
                v[4] = NEG_INF; v[5] = NEG_INF; v[6] = NEG_INF; v[7] = NEG_INF;
            }
        } else {
#pragma unroll
            for (int q = 0; q < 8; q++) v[q] = NEG_INF;
        }

        // Input row r contributes to output rows oh = r - i, i = 0..4.
        // i == 0 (oh == r) is that output row's FIRST contribution: assign
        // the tree result directly (no -inf init, no extra max).
#pragma unroll
        for (int i = 0; i < 5; i++) {
            const int oh = r - i;
            if (oh >= 0 && oh < 8) {        // compile-time after unroll
                const int s = oh % 5;
                const float w0 = wf[i * 5 + 0];
                const float w1 = wf[i * 5 + 1];
                const float w2 = wf[i * 5 + 2];
                const float w3 = wf[i * 5 + 3];
                const float w4 = wf[i * 5 + 4];
#pragma unroll
                for (int q = 0; q < 4; q++) {
                    const float t0 = v[q + 0] + w0;
                    const float t1 = v[q + 1] + w1;
                    const float t2 = v[q + 2] + w2;
                    const float t3 = v[q + 3] + w3;
                    const float t4 = v[q + 4] + w4;
                    const float m  = fmaxf(fmaxf(t0, t1), t2);   // -> FMNMX3
                    if (i == 0) {
                        acc[s][q] = fmaxf(m, fmaxf(t3, t4));
                    } else {
                        const float n = fmaxf(fmaxf(t3, t4), acc[s][q]); // -> FMNMX3
                        acc[s][q] = fmaxf(m, n);
                    }
                }
            }
        }

        // Output row oh = r - 4 is complete after this input row: store it.
        if (r >= 4) {
            const int oh = r - 4;
            const int s  = oh % 5;
            float* orow  = op_base + oh * HW;
            if (tx > 0) {
                float2 t; t.x = acc[s][0]; t.y = acc[s][1];
                *reinterpret_cast<float2*>(orow) = t;
            }
            if (tx < 56) {
                float2 t; t.x = acc[s][2]; t.y = acc[s][3];
                *reinterpret_cast<float2*>(orow + 2) = t;
            }
        }
    }
}

extern "C" void kernel_launch(void* const* d_in, const int* in_sizes, int n_in,
                              void* d_out, int out_size)
{
    const float* x = (const float*)d_in[0];
    const float* w = (const float*)d_in[1];
    float* out     = (float*)d_out;
    // 256 planes * 28 row-groups * 57 col-groups = 408576 threads = 1596 blocks
    tropical_conv_kernel<<<1596, 256>>>(x, w, out);
}